// round 1
// baseline (speedup 1.0000x reference)
#include <cuda_runtime.h>
#include <cstdint>

#define N_TOK 8192
#define DIM   1024
#define S_SEM 8192
#define L_LRN 128
#define NC    (S_SEM + L_LRN)   // 8320

// Scratch (device globals — no allocation APIs allowed)
__device__ float g_xn[(size_t)N_TOK * DIM];
__device__ float g_cb[(size_t)NC * DIM];
__device__ unsigned long long g_best[N_TOK];

// ---------------- helpers ----------------

// Order-preserving float -> uint map (monotonic: a<b  <=>  fkey(a)<fkey(b))
__device__ __forceinline__ unsigned int fkey(float f) {
    unsigned int u = __float_as_uint(f);
    return (u & 0x80000000u) ? ~u : (u | 0x80000000u);
}
__device__ __forceinline__ float fkey_inv(unsigned int k) {
    return __uint_as_float((k & 0x80000000u) ? (k ^ 0x80000000u) : ~k);
}

// Packed f32x2 FMA (Blackwell FFMA2 — only reachable via PTX fma.rn.f32x2)
__device__ __forceinline__ float2 ffma2(float2 a, float2 b, float2 c) {
    float2 d;
    asm("{\n\t"
        ".reg .b64 ra, rb, rc;\n\t"
        "mov.b64 ra, {%2, %3};\n\t"
        "mov.b64 rb, {%4, %5};\n\t"
        "mov.b64 rc, {%6, %7};\n\t"
        "fma.rn.f32x2 rc, ra, rb, rc;\n\t"
        "mov.b64 {%0, %1}, rc;\n\t"
        "}"
        : "=f"(d.x), "=f"(d.y)
        : "f"(a.x), "f"(a.y), "f"(b.x), "f"(b.y), "f"(c.x), "f"(c.y));
    return d;
}

// ---------------- normalize rows ----------------
// mode 0: x -> g_xn (also zero g_best[row])
// mode 1: semantic -> g_cb[0:S]
// mode 2: learnable -> g_cb[S:S+L]
__global__ void normalize_kernel(const float* __restrict__ src, int mode) {
    int row = blockIdx.x;
    int tid = threadIdx.x;

    const float4* s = (const float4*)(src + (size_t)row * DIM);
    float4 v = s[tid];
    float ss = v.x * v.x + v.y * v.y + v.z * v.z + v.w * v.w;

    // warp reduce
    #pragma unroll
    for (int off = 16; off > 0; off >>= 1)
        ss += __shfl_down_sync(0xffffffffu, ss, off);

    __shared__ float ws[8];
    __shared__ float s_scale;
    int lane = tid & 31, wid = tid >> 5;
    if (lane == 0) ws[wid] = ss;
    __syncthreads();
    if (tid == 0) {
        float t = 0.f;
        #pragma unroll
        for (int i = 0; i < 8; i++) t += ws[i];
        s_scale = 1.0f / fmaxf(sqrtf(t), 1e-8f);
    }
    __syncthreads();
    float sc = s_scale;

    float* dst;
    if (mode == 0)      dst = g_xn + (size_t)row * DIM;
    else if (mode == 1) dst = g_cb + (size_t)row * DIM;
    else                dst = g_cb + (size_t)(S_SEM + row) * DIM;

    float4 o = make_float4(v.x * sc, v.y * sc, v.z * sc, v.w * sc);
    ((float4*)dst)[tid] = o;

    if (mode == 0 && tid == 0) g_best[row] = 0ull;
}

// ---------------- GEMM (128x128x16 tiles, f32x2 FMA) + fused argmax ----------------
#define BM 128
#define BN 128
#define BK 16

__global__ __launch_bounds__(256, 2)
void gemm_argmax_kernel(float* __restrict__ C) {
    __shared__ float As[BK][BM];
    __shared__ float Bs[BK][BN];

    const int tid = threadIdx.x;
    const int bm = blockIdx.y;
    const int bn = blockIdx.x;

    const int tm0 = (tid >> 4) * 8;   // 0..120
    const int tn0 = (tid & 15) * 8;   // 0..120

    float2 acc[8][4];
    #pragma unroll
    for (int m = 0; m < 8; m++)
        #pragma unroll
        for (int j = 0; j < 4; j++)
            acc[m][j] = make_float2(0.f, 0.f);

    const int lr = tid >> 2;         // 0..63
    const int lc = (tid & 3) * 4;    // 0,4,8,12
    const float* Ag = g_xn + (size_t)(bm * BM) * DIM;
    const float* Bg = g_cb + (size_t)(bn * BN) * DIM;

    for (int kt = 0; kt < DIM; kt += BK) {
        #pragma unroll
        for (int p = 0; p < 2; p++) {
            int r = lr + p * 64;
            float4 va = *(const float4*)(Ag + (size_t)r * DIM + kt + lc);
            As[lc + 0][r] = va.x; As[lc + 1][r] = va.y;
            As[lc + 2][r] = va.z; As[lc + 3][r] = va.w;
            float4 vb = *(const float4*)(Bg + (size_t)r * DIM + kt + lc);
            Bs[lc + 0][r] = vb.x; Bs[lc + 1][r] = vb.y;
            Bs[lc + 2][r] = vb.z; Bs[lc + 3][r] = vb.w;
        }
        __syncthreads();

        #pragma unroll
        for (int k = 0; k < BK; k++) {
            float4 a0 = *(const float4*)&As[k][tm0];
            float4 a1 = *(const float4*)&As[k][tm0 + 4];
            float4 b0 = *(const float4*)&Bs[k][tn0];
            float4 b1 = *(const float4*)&Bs[k][tn0 + 4];
            float av[8] = {a0.x, a0.y, a0.z, a0.w, a1.x, a1.y, a1.z, a1.w};
            float2 b2[4] = {make_float2(b0.x, b0.y), make_float2(b0.z, b0.w),
                            make_float2(b1.x, b1.y), make_float2(b1.z, b1.w)};
            #pragma unroll
            for (int m = 0; m < 8; m++) {
                float2 aa = make_float2(av[m], av[m]);
                #pragma unroll
                for (int j = 0; j < 4; j++)
                    acc[m][j] = ffma2(aa, b2[j], acc[m][j]);
            }
        }
        __syncthreads();
    }

    // epilogue: store logits + fused per-row argmax
    const int nbase = bn * BN + tn0;
    #pragma unroll
    for (int m = 0; m < 8; m++) {
        int row = bm * BM + tm0 + m;
        float vals[8] = {acc[m][0].x, acc[m][0].y, acc[m][1].x, acc[m][1].y,
                         acc[m][2].x, acc[m][2].y, acc[m][3].x, acc[m][3].y};
        float4 c0 = make_float4(vals[0], vals[1], vals[2], vals[3]);
        float4 c1 = make_float4(vals[4], vals[5], vals[6], vals[7]);
        float* crow = C + (size_t)row * NC + nbase;
        *(float4*)(crow)     = c0;
        *(float4*)(crow + 4) = c1;

        unsigned long long k64 = 0ull;
        #pragma unroll
        for (int j = 0; j < 8; j++) {
            unsigned long long key =
                ((unsigned long long)fkey(vals[j]) << 32) |
                (unsigned int)(~(unsigned int)(nbase + j));
            k64 = (key > k64) ? key : k64;
        }
        // reduce over the 16 threads sharing this row group (16-lane segments)
        #pragma unroll
        for (int off = 8; off > 0; off >>= 1) {
            unsigned long long o = __shfl_down_sync(0xffffffffu, k64, off, 16);
            k64 = (o > k64) ? o : k64;
        }
        if ((tid & 15) == 0) atomicMax(&g_best[row], k64);
    }
}

// ---------------- gather z_q / z_q_st / indices ----------------
__global__ void gather_kernel(float* __restrict__ idx_out,
                              float* __restrict__ zq,
                              float* __restrict__ zqst) {
    int row = blockIdx.x;
    unsigned long long k = g_best[row];
    unsigned int idx = ~(unsigned int)(k & 0xffffffffu);
    if (threadIdx.x == 0) idx_out[row] = (float)idx;

    float4 v = ((const float4*)(g_cb + (size_t)idx * DIM))[threadIdx.x];
    ((float4*)(zq   + (size_t)row * DIM))[threadIdx.x] = v;
    ((float4*)(zqst + (size_t)row * DIM))[threadIdx.x] = v;
}

// ---------------- losses (single block, deterministic fixed-order reduce) ----------------
__global__ void loss_kernel(float* __restrict__ out3) {
    __shared__ float s_c[256], s_v[256], s_n[256];
    int tid = threadIdx.x;
    float c = 0.f, v = 0.f, n = 0.f;
    for (int r = tid; r < N_TOK; r += 256) {
        unsigned long long k = g_best[r];
        unsigned int idx = ~(unsigned int)(k & 0xffffffffu);
        float val = fkey_inv((unsigned int)(k >> 32));
        float d = 1.0f - val;
        c += d;
        if (idx >= S_SEM) { v += d; n += 1.0f; }
    }
    s_c[tid] = c; s_v[tid] = v; s_n[tid] = n;
    __syncthreads();
    for (int s = 128; s > 0; s >>= 1) {
        if (tid < s) {
            s_c[tid] += s_c[tid + s];
            s_v[tid] += s_v[tid + s];
            s_n[tid] += s_n[tid + s];
        }
        __syncthreads();
    }
    if (tid == 0) {
        float commit = s_c[0] / (float)N_TOK;
        float vq = s_v[0] / (s_n[0] + 1e-6f);
        out3[0] = vq;                 // vq_loss
        out3[1] = commit;             // commitment_loss
        out3[2] = vq + 0.25f * commit; // quant_loss
    }
}

// ---------------- launch ----------------
extern "C" void kernel_launch(void* const* d_in, const int* in_sizes, int n_in,
                              void* d_out, int out_size) {
    const float* x   = (const float*)d_in[0];
    const float* sem = (const float*)d_in[1];
    const float* lrn = (const float*)d_in[2];
    float* out = (float*)d_out;

    float* logits = out;
    float* idxf   = logits + (size_t)N_TOK * NC;
    float* zq     = idxf + N_TOK;
    float* zqst   = zq + (size_t)N_TOK * DIM;
    float* sc3    = zqst + (size_t)N_TOK * DIM;

    normalize_kernel<<<N_TOK, 256>>>(x, 0);
    normalize_kernel<<<S_SEM, 256>>>(sem, 1);
    normalize_kernel<<<L_LRN, 256>>>(lrn, 2);

    dim3 grid(NC / BN, N_TOK / BM);  // (65, 64)
    gemm_argmax_kernel<<<grid, 256>>>(logits);

    gather_kernel<<<N_TOK, 256>>>(idxf, zq, zqst);
    loss_kernel<<<1, 256>>>(sc3);
}

// round 3
// speedup vs baseline: 1.9732x; 1.9732x over previous
#include <cuda_runtime.h>
#include <cuda_bf16.h>
#include <cstdint>

#define N_TOK 8192
#define DIM   1024
#define S_SEM 8192
#define L_LRN 128
#define NC    (S_SEM + L_LRN)   // 8320

// ---------------- device scratch (static, no runtime alloc) ----------------
__device__ float g_xn[(size_t)N_TOK * DIM];
__device__ float g_cb[(size_t)NC * DIM];
__device__ __nv_bfloat16 g_a1[(size_t)N_TOK * DIM];
__device__ __nv_bfloat16 g_a2[(size_t)N_TOK * DIM];
__device__ __nv_bfloat16 g_b1[(size_t)NC * DIM];
__device__ __nv_bfloat16 g_b2[(size_t)NC * DIM];
__device__ unsigned long long g_best[N_TOK];

// ---------------- helpers ----------------
__device__ __forceinline__ unsigned int fkey(float f) {
    unsigned int u = __float_as_uint(f);
    return (u & 0x80000000u) ? ~u : (u | 0x80000000u);
}
__device__ __forceinline__ float fkey_inv(unsigned int k) {
    return __uint_as_float((k & 0x80000000u) ? (k ^ 0x80000000u) : ~k);
}
__device__ __forceinline__ uint32_t smem_u32(const void* p) {
    uint32_t a;
    asm("{ .reg .u64 t; cvta.to.shared.u64 t, %1; cvt.u32.u64 %0, t; }" : "=r"(a) : "l"(p));
    return a;
}
__device__ __forceinline__ void cp16(uint32_t dst, const void* src) {
    asm volatile("cp.async.cg.shared.global [%0], [%1], 16;" :: "r"(dst), "l"(src));
}
__device__ __forceinline__ void ldsm4(uint32_t* r, uint32_t addr) {
    asm volatile("ldmatrix.sync.aligned.m8n8.x4.shared.b16 {%0,%1,%2,%3}, [%4];"
        : "=r"(r[0]), "=r"(r[1]), "=r"(r[2]), "=r"(r[3]) : "r"(addr));
}
__device__ __forceinline__ void ldsm2(uint32_t* r, uint32_t addr) {
    asm volatile("ldmatrix.sync.aligned.m8n8.x2.shared.b16 {%0,%1}, [%2];"
        : "=r"(r[0]), "=r"(r[1]) : "r"(addr));
}
__device__ __forceinline__ void mma16816(float* c, const uint32_t* a, const uint32_t* b) {
    asm volatile(
        "mma.sync.aligned.m16n8k16.row.col.f32.bf16.bf16.f32 "
        "{%0,%1,%2,%3}, {%4,%5,%6,%7}, {%8,%9}, {%0,%1,%2,%3};"
        : "+f"(c[0]), "+f"(c[1]), "+f"(c[2]), "+f"(c[3])
        : "r"(a[0]), "r"(a[1]), "r"(a[2]), "r"(a[3]), "r"(b[0]), "r"(b[1]));
}

// ---------------- normalize + bf16 hi/lo split ----------------
__global__ void normalize_kernel(const float* __restrict__ src, int mode) {
    int row = blockIdx.x;
    int tid = threadIdx.x;

    float4 v = ((const float4*)(src + (size_t)row * DIM))[tid];
    float ss = v.x * v.x + v.y * v.y + v.z * v.z + v.w * v.w;
    #pragma unroll
    for (int off = 16; off > 0; off >>= 1) ss += __shfl_down_sync(0xffffffffu, ss, off);

    __shared__ float ws[8];
    __shared__ float s_scale;
    int lane = tid & 31, wid = tid >> 5;
    if (lane == 0) ws[wid] = ss;
    __syncthreads();
    if (tid == 0) {
        float t = 0.f;
        #pragma unroll
        for (int i = 0; i < 8; i++) t += ws[i];
        s_scale = 1.0f / fmaxf(sqrtf(t), 1e-8f);
    }
    __syncthreads();
    float sc = s_scale;
    float4 o = make_float4(v.x * sc, v.y * sc, v.z * sc, v.w * sc);

    size_t orow = (mode == 2) ? (size_t)(S_SEM + row) : (size_t)row;
    float* fdst = (mode == 0) ? g_xn : g_cb;
    ((float4*)(fdst + orow * DIM))[tid] = o;

    __nv_bfloat16 h[4], l[4];
    float vv[4] = {o.x, o.y, o.z, o.w};
    #pragma unroll
    for (int i = 0; i < 4; i++) {
        h[i] = __float2bfloat16(vv[i]);
        l[i] = __float2bfloat16(vv[i] - __bfloat162float(h[i]));
    }
    ushort4 ph = make_ushort4(__bfloat16_as_ushort(h[0]), __bfloat16_as_ushort(h[1]),
                              __bfloat16_as_ushort(h[2]), __bfloat16_as_ushort(h[3]));
    ushort4 pl = make_ushort4(__bfloat16_as_ushort(l[0]), __bfloat16_as_ushort(l[1]),
                              __bfloat16_as_ushort(l[2]), __bfloat16_as_ushort(l[3]));
    __nv_bfloat16* hdst = (mode == 0) ? g_a1 : g_b1;
    __nv_bfloat16* ldst = (mode == 0) ? g_a2 : g_b2;
    ((ushort4*)hdst)[orow * (DIM / 4) + tid] = ph;
    ((ushort4*)ldst)[orow * (DIM / 4) + tid] = pl;

    if (mode == 0 && tid == 0) g_best[row] = 0ull;
}

// ---------------- mma.sync GEMM (bf16x3) + fused argmax ----------------
#define BM 128
#define BN 128
#define BK 32
#define STAGES 3
#define PAD 40                       // row stride in elems (80B: 16B-aligned, odd*16 -> conflict-free)
#define MAT_BYTES (128 * PAD * 2)    // 10240
#define STG_BYTES (4 * MAT_BYTES)    // 40960
#define OFF_A1 0
#define OFF_A2 (1 * MAT_BYTES)
#define OFF_B1 (2 * MAT_BYTES)
#define OFF_B2 (3 * MAT_BYTES)
#define KTILES (DIM / BK)            // 32
#define SMEM_TOTAL (STAGES * STG_BYTES)  // 122880

__global__ __launch_bounds__(256, 1)
void gemm_mma_kernel(float* __restrict__ C) {
    extern __shared__ char smem[];
    const uint32_t sb = smem_u32(smem);
    const int tid = threadIdx.x;
    const int lane = tid & 31;
    const int w = tid >> 5;
    const int warp_m = w >> 2;   // 0..1
    const int warp_n = w & 3;    // 0..3
    const int bm = blockIdx.y;
    const int bn = blockIdx.x;

    // cp.async assignment: thread covers 32B of one row in each of 4 matrices
    const int lrow = tid >> 1;            // 0..127
    const int lk = (tid & 1) * 16;        // elem offset 0/16
    const size_t gA = ((size_t)(bm * BM + lrow)) * DIM + lk;
    const size_t gB = ((size_t)(bn * BN + lrow)) * DIM + lk;
    const uint32_t sOff = (uint32_t)(lrow * PAD + lk) * 2;

    float c[4][4][4];
    #pragma unroll
    for (int mi = 0; mi < 4; mi++)
        #pragma unroll
        for (int ni = 0; ni < 4; ni++)
            #pragma unroll
            for (int j = 0; j < 4; j++) c[mi][ni][j] = 0.f;

    // prologue: load stages 0,1
    #pragma unroll
    for (int s = 0; s < 2; s++) {
        const uint32_t st = sb + s * STG_BYTES;
        const int kt = s * BK;
        cp16(st + OFF_A1 + sOff,      g_a1 + gA + kt);
        cp16(st + OFF_A1 + sOff + 16, g_a1 + gA + kt + 8);
        cp16(st + OFF_A2 + sOff,      g_a2 + gA + kt);
        cp16(st + OFF_A2 + sOff + 16, g_a2 + gA + kt + 8);
        cp16(st + OFF_B1 + sOff,      g_b1 + gB + kt);
        cp16(st + OFF_B1 + sOff + 16, g_b1 + gB + kt + 8);
        cp16(st + OFF_B2 + sOff,      g_b2 + gB + kt);
        cp16(st + OFF_B2 + sOff + 16, g_b2 + gB + kt + 8);
        asm volatile("cp.async.commit_group;" ::: "memory");
    }

    // fragment smem address bases (per lane)
    const uint32_t aRow = (uint32_t)(warp_m * 64 + (lane & 15)) * (PAD * 2) + ((lane >> 4) << 4);
    const uint32_t bRow = (uint32_t)(warp_n * 32 + (lane & 7)) * (PAD * 2) + (((lane >> 3) & 1) << 4);

    for (int it = 0; it < KTILES; it++) {
        asm volatile("cp.async.wait_group 1;" ::: "memory");
        __syncthreads();

        const uint32_t st = sb + (it % STAGES) * STG_BYTES;
        #pragma unroll
        for (int ks = 0; ks < 2; ks++) {
            const uint32_t kb = ks * 32;   // 16 elems = 32 bytes
            uint32_t a1f[4][4], a2f[4][4], b1f[4][2], b2f[4][2];
            #pragma unroll
            for (int mi = 0; mi < 4; mi++) {
                uint32_t ad = st + aRow + (uint32_t)(mi * 16) * (PAD * 2) + kb;
                ldsm4(a1f[mi], ad + OFF_A1);
                ldsm4(a2f[mi], ad + OFF_A2);
            }
            #pragma unroll
            for (int ni = 0; ni < 4; ni++) {
                uint32_t bd = st + bRow + (uint32_t)(ni * 8) * (PAD * 2) + kb;
                ldsm2(b1f[ni], bd + OFF_B1);
                ldsm2(b2f[ni], bd + OFF_B2);
            }
            #pragma unroll
            for (int mi = 0; mi < 4; mi++)
                #pragma unroll
                for (int ni = 0; ni < 4; ni++) {
                    mma16816(c[mi][ni], a1f[mi], b1f[ni]);
                    mma16816(c[mi][ni], a1f[mi], b2f[ni]);
                    mma16816(c[mi][ni], a2f[mi], b1f[ni]);
                }
        }
        __syncthreads();

        if (it + 2 < KTILES) {
            const int s2 = (it + 2) % STAGES;
            const uint32_t st2 = sb + s2 * STG_BYTES;
            const int kt = (it + 2) * BK;
            cp16(st2 + OFF_A1 + sOff,      g_a1 + gA + kt);
            cp16(st2 + OFF_A1 + sOff + 16, g_a1 + gA + kt + 8);
            cp16(st2 + OFF_A2 + sOff,      g_a2 + gA + kt);
            cp16(st2 + OFF_A2 + sOff + 16, g_a2 + gA + kt + 8);
            cp16(st2 + OFF_B1 + sOff,      g_b1 + gB + kt);
            cp16(st2 + OFF_B1 + sOff + 16, g_b1 + gB + kt + 8);
            cp16(st2 + OFF_B2 + sOff,      g_b2 + gB + kt);
            cp16(st2 + OFF_B2 + sOff + 16, g_b2 + gB + kt + 8);
        }
        asm volatile("cp.async.commit_group;" ::: "memory");
    }

    // ---------------- epilogue: store + fused argmax ----------------
    const int g = lane >> 2, q = lane & 3;
    #pragma unroll
    for (int mi = 0; mi < 4; mi++) {
        #pragma unroll
        for (int half = 0; half < 2; half++) {
            const int row = bm * BM + warp_m * 64 + mi * 16 + g + half * 8;
            float* crow = C + (size_t)row * NC + bn * BN + warp_n * 32;
            unsigned long long key = 0ull;
            #pragma unroll
            for (int ni = 0; ni < 4; ni++) {
                float v0 = c[mi][ni][half * 2 + 0];
                float v1 = c[mi][ni][half * 2 + 1];
                int col0 = bn * BN + warp_n * 32 + ni * 8 + q * 2;
                unsigned long long k0 = ((unsigned long long)fkey(v0) << 32) |
                                        (unsigned int)(~(unsigned int)col0);
                unsigned long long k1 = ((unsigned long long)fkey(v1) << 32) |
                                        (unsigned int)(~(unsigned int)(col0 + 1));
                key = (k0 > key) ? k0 : key;
                key = (k1 > key) ? k1 : key;
                *(float2*)(crow + ni * 8 + q * 2) = make_float2(v0, v1);
            }
            unsigned long long o1 = __shfl_xor_sync(0xffffffffu, key, 1);
            key = (o1 > key) ? o1 : key;
            unsigned long long o2 = __shfl_xor_sync(0xffffffffu, key, 2);
            key = (o2 > key) ? o2 : key;
            if (q == 0) atomicMax(&g_best[row], key);
        }
    }
}

// ---------------- rescue: exact fp32 re-check of near-tied rows ----------------
__global__ void rescue_kernel(const float* __restrict__ C) {
    const int row = blockIdx.x;
    const int tid = threadIdx.x;
    __shared__ int s_cnt;
    __shared__ int s_idx[32];
    __shared__ float s_red[256];
    __shared__ unsigned long long s_best;

    unsigned long long k0 = g_best[row];
    float amax = fkey_inv((unsigned int)(k0 >> 32));
    float thresh = amax - 1e-4f;
    if (tid == 0) { s_cnt = 0; s_best = 0ull; }
    __syncthreads();

    const float* rowp = C + (size_t)row * NC;
    for (int j = tid; j < NC; j += 256) {
        float v = rowp[j];
        if (v > thresh) {
            int p = atomicAdd(&s_cnt, 1);
            if (p < 32) s_idx[p] = j;
        }
    }
    __syncthreads();
    int cnt = s_cnt < 32 ? s_cnt : 32;
    if (cnt <= 1) return;

    const float* xr = g_xn + (size_t)row * DIM;
    for (int ci = 0; ci < cnt; ci++) {
        int idx = s_idx[ci];
        const float* cbr = g_cb + (size_t)idx * DIM;
        float p = 0.f;
        #pragma unroll
        for (int e = 0; e < 4; e++) p += xr[tid * 4 + e] * cbr[tid * 4 + e];
        s_red[tid] = p;
        __syncthreads();
        for (int s = 128; s > 0; s >>= 1) {
            if (tid < s) s_red[tid] += s_red[tid + s];
            __syncthreads();
        }
        if (tid == 0) {
            unsigned long long key = ((unsigned long long)fkey(s_red[0]) << 32) |
                                     (unsigned int)(~(unsigned int)idx);
            if (key > s_best) s_best = key;
        }
        __syncthreads();
    }
    if (tid == 0) g_best[row] = s_best;
}

// ---------------- gather z_q / z_q_st / indices ----------------
__global__ void gather_kernel(float* __restrict__ idx_out,
                              float* __restrict__ zq,
                              float* __restrict__ zqst) {
    int row = blockIdx.x;
    unsigned long long k = g_best[row];
    unsigned int idx = ~(unsigned int)(k & 0xffffffffu);
    if (threadIdx.x == 0) idx_out[row] = (float)idx;
    float4 v = ((const float4*)(g_cb + (size_t)idx * DIM))[threadIdx.x];
    ((float4*)(zq   + (size_t)row * DIM))[threadIdx.x] = v;
    ((float4*)(zqst + (size_t)row * DIM))[threadIdx.x] = v;
}

// ---------------- losses ----------------
__global__ void loss_kernel(float* __restrict__ out3) {
    __shared__ float s_c[256], s_v[256], s_n[256];
    int tid = threadIdx.x;
    float c = 0.f, v = 0.f, n = 0.f;
    for (int r = tid; r < N_TOK; r += 256) {
        unsigned long long k = g_best[r];
        unsigned int idx = ~(unsigned int)(k & 0xffffffffu);
        float val = fkey_inv((unsigned int)(k >> 32));
        float d = 1.0f - val;
        c += d;
        if (idx >= S_SEM) { v += d; n += 1.0f; }
    }
    s_c[tid] = c; s_v[tid] = v; s_n[tid] = n;
    __syncthreads();
    for (int s = 128; s > 0; s >>= 1) {
        if (tid < s) {
            s_c[tid] += s_c[tid + s];
            s_v[tid] += s_v[tid + s];
            s_n[tid] += s_n[tid + s];
        }
        __syncthreads();
    }
    if (tid == 0) {
        float commit = s_c[0] / (float)N_TOK;
        float vq = s_v[0] / (s_n[0] + 1e-6f);
        out3[0] = vq;
        out3[1] = commit;
        out3[2] = vq + 0.25f * commit;
    }
}

// ---------------- launch ----------------
extern "C" void kernel_launch(void* const* d_in, const int* in_sizes, int n_in,
                              void* d_out, int out_size) {
    const float* x   = (const float*)d_in[0];
    const float* sem = (const float*)d_in[1];
    const float* lrn = (const float*)d_in[2];
    float* out = (float*)d_out;

    float* logits = out;
    float* idxf   = logits + (size_t)N_TOK * NC;
    float* zq     = idxf + N_TOK;
    float* zqst   = zq + (size_t)N_TOK * DIM;
    float* sc3    = zqst + (size_t)N_TOK * DIM;

    cudaFuncSetAttribute(gemm_mma_kernel,
                         cudaFuncAttributeMaxDynamicSharedMemorySize, SMEM_TOTAL);

    normalize_kernel<<<N_TOK, 256>>>(x, 0);
    normalize_kernel<<<S_SEM, 256>>>(sem, 1);
    normalize_kernel<<<L_LRN, 256>>>(lrn, 2);

    dim3 grid(NC / BN, N_TOK / BM);   // (65, 64)
    gemm_mma_kernel<<<grid, 256, SMEM_TOTAL>>>(logits);

    rescue_kernel<<<N_TOK, 256>>>(logits);
    gather_kernel<<<N_TOK, 256>>>(idxf, zq, zqst);
    loss_kernel<<<1, 256>>>(sc3);
}

// round 5
// speedup vs baseline: 5.5647x; 2.8201x over previous
#include <cuda_runtime.h>
#include <cuda_fp16.h>
#include <cstdint>

#define N_TOK 8192
#define DIM   1024
#define S_SEM 8192
#define L_LRN 128
#define NC    (S_SEM + L_LRN)   // 8320
#define NC_PAD 8448             // padded to multiple of 256

// ---------------- device scratch (zero-initialized device globals) ----------------
__device__ float g_xn[(size_t)N_TOK * DIM];
__device__ float g_cb[(size_t)NC * DIM];
__device__ __half g_ah[(size_t)N_TOK * DIM];
__device__ __half g_bh[(size_t)NC_PAD * DIM];   // rows >= NC stay zero forever
__device__ unsigned long long g_best[N_TOK];

// ---------------- helpers ----------------
__device__ __forceinline__ unsigned int fkey(float f) {
    unsigned int u = __float_as_uint(f);
    return (u & 0x80000000u) ? ~u : (u | 0x80000000u);
}
__device__ __forceinline__ float fkey_inv(unsigned int k) {
    return __uint_as_float((k & 0x80000000u) ? (k ^ 0x80000000u) : ~k);
}
__device__ __forceinline__ uint32_t smem_u32(const void* p) {
    uint32_t a;
    asm("{ .reg .u64 t; cvta.to.shared.u64 t, %1; cvt.u32.u64 %0, t; }" : "=r"(a) : "l"(p));
    return a;
}
__device__ __forceinline__ void cp16(uint32_t dst, const void* src) {
    asm volatile("cp.async.cg.shared.global [%0], [%1], 16;" :: "r"(dst), "l"(src));
}
__device__ __forceinline__ void ldsm4(uint32_t* r, uint32_t addr) {
    asm volatile("ldmatrix.sync.aligned.m8n8.x4.shared.b16 {%0,%1,%2,%3}, [%4];"
        : "=r"(r[0]), "=r"(r[1]), "=r"(r[2]), "=r"(r[3]) : "r"(addr));
}
__device__ __forceinline__ void ldsm2(uint32_t* r, uint32_t addr) {
    asm volatile("ldmatrix.sync.aligned.m8n8.x2.shared.b16 {%0,%1}, [%2];"
        : "=r"(r[0]), "=r"(r[1]) : "r"(addr));
}
__device__ __forceinline__ void mma16816(float* c, const uint32_t* a, const uint32_t* b) {
    asm volatile(
        "mma.sync.aligned.m16n8k16.row.col.f32.f16.f16.f32 "
        "{%0,%1,%2,%3}, {%4,%5,%6,%7}, {%8,%9}, {%0,%1,%2,%3};"
        : "+f"(c[0]), "+f"(c[1]), "+f"(c[2]), "+f"(c[3])
        : "r"(a[0]), "r"(a[1]), "r"(a[2]), "r"(a[3]), "r"(b[0]), "r"(b[1]));
}

// ---------------- normalize + fp16 convert ----------------
// mode 0: x -> g_xn + g_ah (+ reset g_best)
// mode 1: semantic -> g_cb[0:S] + g_bh
// mode 2: learnable -> g_cb[S:] + g_bh (offset S)
__global__ void normalize_kernel(const float* __restrict__ src, int mode) {
    int row = blockIdx.x;
    int tid = threadIdx.x;

    float4 v = ((const float4*)(src + (size_t)row * DIM))[tid];
    float ss = v.x * v.x + v.y * v.y + v.z * v.z + v.w * v.w;
    #pragma unroll
    for (int off = 16; off > 0; off >>= 1) ss += __shfl_down_sync(0xffffffffu, ss, off);

    __shared__ float ws[8];
    __shared__ float s_scale;
    int lane = tid & 31, wid = tid >> 5;
    if (lane == 0) ws[wid] = ss;
    __syncthreads();
    if (tid == 0) {
        float t = 0.f;
        #pragma unroll
        for (int i = 0; i < 8; i++) t += ws[i];
        s_scale = 1.0f / fmaxf(sqrtf(t), 1e-8f);
    }
    __syncthreads();
    float sc = s_scale;
    float4 o = make_float4(v.x * sc, v.y * sc, v.z * sc, v.w * sc);

    size_t orow = (mode == 2) ? (size_t)(S_SEM + row) : (size_t)row;
    float* fdst = (mode == 0) ? g_xn : g_cb;
    ((float4*)(fdst + orow * DIM))[tid] = o;

    __half2 h0 = make_half2(__float2half_rn(o.x), __float2half_rn(o.y));
    __half2 h1 = make_half2(__float2half_rn(o.z), __float2half_rn(o.w));
    __half* hdst = (mode == 0) ? g_ah : g_bh;
    ((uint2*)(hdst + orow * DIM))[tid] =
        make_uint2(*(uint32_t*)&h0, *(uint32_t*)&h1);

    if (mode == 0 && tid == 0) g_best[row] = 0ull;
}

// ---------------- fp16 mma GEMM + fused argmax ----------------
#define BM 128
#define BN 256
#define BK 32
#define STAGES 4
#define PAD 40                        // elems per smem row (80B stride)
#define PADB (PAD * 2)
#define OFF_A 0
#define OFF_B (128 * PADB)            // 10240
#define STG_BYTES ((128 + 256) * PADB)  // 30720
#define KTILES (DIM / BK)             // 32
#define SMEM_TOTAL (STAGES * STG_BYTES) // 122880

__device__ __forceinline__ void load_stage(uint32_t st, int tid, int kt,
                                           size_t rowA0, size_t rowB0) {
    // A: 128 rows x 64B (4 chunks of 16B): 512 chunks, 2 per thread
    #pragma unroll
    for (int i = 0; i < 2; i++) {
        int idx = tid + i * 256;
        int r = idx >> 2, ch = idx & 3;
        cp16(st + OFF_A + (uint32_t)(r * PADB + ch * 16),
             g_ah + (rowA0 + r) * DIM + kt + ch * 8);
    }
    // B: 256 rows: 1024 chunks, 4 per thread
    #pragma unroll
    for (int i = 0; i < 4; i++) {
        int idx = tid + i * 256;
        int r = idx >> 2, ch = idx & 3;
        cp16(st + OFF_B + (uint32_t)(r * PADB + ch * 16),
             g_bh + (rowB0 + r) * DIM + kt + ch * 8);
    }
    asm volatile("cp.async.commit_group;" ::: "memory");
}

__global__ __launch_bounds__(256, 1)
void gemm_mma_kernel(float* __restrict__ C) {
    extern __shared__ char smem[];
    const uint32_t sb = smem_u32(smem);
    const int tid = threadIdx.x;
    const int lane = tid & 31;
    const int w = tid >> 5;
    const int warp_m = w >> 2;   // 0..1 (rows)
    const int warp_n = w & 3;    // 0..3 (cols)
    const int bm = blockIdx.y;
    const int bn = blockIdx.x;   // 0..32

    const size_t rowA0 = (size_t)bm * BM;
    const size_t rowB0 = (size_t)bn * BN;

    float c[4][8][4];
    #pragma unroll
    for (int mi = 0; mi < 4; mi++)
        #pragma unroll
        for (int ni = 0; ni < 8; ni++)
            #pragma unroll
            for (int j = 0; j < 4; j++) c[mi][ni][j] = 0.f;

    // prologue: stages 0..2
    #pragma unroll
    for (int s = 0; s < 3; s++)
        load_stage(sb + s * STG_BYTES, tid, s * BK, rowA0, rowB0);

    const uint32_t aBase = sb + OFF_A +
        (uint32_t)(warp_m * 64 + (lane & 15)) * PADB + ((lane >> 4) << 4);
    const uint32_t bBase = sb + OFF_B +
        (uint32_t)(warp_n * 64 + (lane & 7)) * PADB + (((lane >> 3) & 1) << 4);

    for (int it = 0; it < KTILES; it++) {
        asm volatile("cp.async.wait_group 2;" ::: "memory");
        __syncthreads();

        const uint32_t so = (uint32_t)((it & 3) * STG_BYTES);
        #pragma unroll
        for (int ks = 0; ks < 2; ks++) {
            const uint32_t kb = ks * 32;
            uint32_t af[4][4], bf[8][2];
            #pragma unroll
            for (int mi = 0; mi < 4; mi++)
                ldsm4(af[mi], aBase + so + (uint32_t)(mi * 16) * PADB + kb);
            #pragma unroll
            for (int ni = 0; ni < 8; ni++)
                ldsm2(bf[ni], bBase + so + (uint32_t)(ni * 8) * PADB + kb);
            #pragma unroll
            for (int mi = 0; mi < 4; mi++)
                #pragma unroll
                for (int ni = 0; ni < 8; ni++)
                    mma16816(c[mi][ni], af[mi], bf[ni]);
        }

        if (it + 3 < KTILES)
            load_stage(sb + ((it + 3) & 3) * STG_BYTES, tid, (it + 3) * BK, rowA0, rowB0);
        else
            asm volatile("cp.async.commit_group;" ::: "memory");
    }

    // ---------------- epilogue: store + fused argmax ----------------
    const int g = lane >> 2, q = lane & 3;
    #pragma unroll
    for (int mi = 0; mi < 4; mi++) {
        #pragma unroll
        for (int half = 0; half < 2; half++) {
            const int row = bm * BM + warp_m * 64 + mi * 16 + g + half * 8;
            float* crow = C + (size_t)row * NC;
            unsigned long long key = 0ull;
            #pragma unroll
            for (int ni = 0; ni < 8; ni++) {
                int col0 = bn * BN + warp_n * 64 + ni * 8 + q * 2;
                if (col0 < NC) {
                    float v0 = c[mi][ni][half * 2 + 0];
                    float v1 = c[mi][ni][half * 2 + 1];
                    unsigned long long k0 = ((unsigned long long)fkey(v0) << 32) |
                                            (unsigned int)(~(unsigned int)col0);
                    unsigned long long k1 = ((unsigned long long)fkey(v1) << 32) |
                                            (unsigned int)(~(unsigned int)(col0 + 1));
                    key = (k0 > key) ? k0 : key;
                    key = (k1 > key) ? k1 : key;
                    *(float2*)(crow + col0) = make_float2(v0, v1);
                }
            }
            unsigned long long o1 = __shfl_xor_sync(0xffffffffu, key, 1);
            key = (o1 > key) ? o1 : key;
            unsigned long long o2 = __shfl_xor_sync(0xffffffffu, key, 2);
            key = (o2 > key) ? o2 : key;
            if (q == 0) atomicMax(&g_best[row], key);
        }
    }
}

// ---------------- rescue: exact fp32 re-check of near-tied rows ----------------
#define RESCUE_WIN 3e-4f
#define RESCUE_CAP 64

__global__ void rescue_kernel(const float* __restrict__ C) {
    const int row = blockIdx.x;
    const int tid = threadIdx.x;
    __shared__ int s_cnt;
    __shared__ int s_idx[RESCUE_CAP];
    __shared__ float s_red[256];
    __shared__ unsigned long long s_best;

    unsigned long long k0 = g_best[row];
    float amax = fkey_inv((unsigned int)(k0 >> 32));
    float thresh = amax - RESCUE_WIN;
    if (tid == 0) { s_cnt = 0; s_best = 0ull; }
    __syncthreads();

    const float* rowp = C + (size_t)row * NC;
    for (int j = tid; j < NC; j += 256) {
        float v = rowp[j];
        if (v > thresh) {
            int p = atomicAdd(&s_cnt, 1);
            if (p < RESCUE_CAP) s_idx[p] = j;
        }
    }
    __syncthreads();
    int cnt = s_cnt < RESCUE_CAP ? s_cnt : RESCUE_CAP;
    if (cnt <= 1) return;

    const float* xr = g_xn + (size_t)row * DIM;
    for (int ci = 0; ci < cnt; ci++) {
        int idx = s_idx[ci];
        const float* cbr = g_cb + (size_t)idx * DIM;
        float p = 0.f;
        #pragma unroll
        for (int e = 0; e < 4; e++) p += xr[tid * 4 + e] * cbr[tid * 4 + e];
        s_red[tid] = p;
        __syncthreads();
        for (int s = 128; s > 0; s >>= 1) {
            if (tid < s) s_red[tid] += s_red[tid + s];
            __syncthreads();
        }
        if (tid == 0) {
            unsigned long long key = ((unsigned long long)fkey(s_red[0]) << 32) |
                                     (unsigned int)(~(unsigned int)idx);
            if (key > s_best) s_best = key;
        }
        __syncthreads();
    }
    if (tid == 0) g_best[row] = s_best;
}

// ---------------- gather z_q / z_q_st / indices ----------------
__global__ void gather_kernel(float* __restrict__ idx_out,
                              float* __restrict__ zq,
                              float* __restrict__ zqst) {
    int row = blockIdx.x;
    unsigned long long k = g_best[row];
    unsigned int idx = ~(unsigned int)(k & 0xffffffffu);
    if (threadIdx.x == 0) idx_out[row] = (float)idx;
    float4 v = ((const float4*)(g_cb + (size_t)idx * DIM))[threadIdx.x];
    ((float4*)(zq   + (size_t)row * DIM))[threadIdx.x] = v;
    ((float4*)(zqst + (size_t)row * DIM))[threadIdx.x] = v;
}

// ---------------- losses ----------------
__global__ void loss_kernel(float* __restrict__ out3) {
    __shared__ float s_c[256], s_v[256], s_n[256];
    int tid = threadIdx.x;
    float c = 0.f, v = 0.f, n = 0.f;
    for (int r = tid; r < N_TOK; r += 256) {
        unsigned long long k = g_best[r];
        unsigned int idx = ~(unsigned int)(k & 0xffffffffu);
        float val = fkey_inv((unsigned int)(k >> 32));
        float d = 1.0f - val;
        c += d;
        if (idx >= S_SEM) { v += d; n += 1.0f; }
    }
    s_c[tid] = c; s_v[tid] = v; s_n[tid] = n;
    __syncthreads();
    for (int s = 128; s > 0; s >>= 1) {
        if (tid < s) {
            s_c[tid] += s_c[tid + s];
            s_v[tid] += s_v[tid + s];
            s_n[tid] += s_n[tid + s];
        }
        __syncthreads();
    }
    if (tid == 0) {
        float commit = s_c[0] / (float)N_TOK;
        float vq = s_v[0] / (s_n[0] + 1e-6f);
        out3[0] = vq;
        out3[1] = commit;
        out3[2] = vq + 0.25f * commit;
    }
}

// ---------------- launch ----------------
extern "C" void kernel_launch(void* const* d_in, const int* in_sizes, int n_in,
                              void* d_out, int out_size) {
    const float* x   = (const float*)d_in[0];
    const float* sem = (const float*)d_in[1];
    const float* lrn = (const float*)d_in[2];
    float* out = (float*)d_out;

    float* logits = out;
    float* idxf   = logits + (size_t)N_TOK * NC;
    float* zq     = idxf + N_TOK;
    float* zqst   = zq + (size_t)N_TOK * DIM;
    float* sc3    = zqst + (size_t)N_TOK * DIM;

    cudaFuncSetAttribute(gemm_mma_kernel,
                         cudaFuncAttributeMaxDynamicSharedMemorySize, SMEM_TOTAL);

    normalize_kernel<<<N_TOK, 256>>>(x, 0);
    normalize_kernel<<<S_SEM, 256>>>(sem, 1);
    normalize_kernel<<<L_LRN, 256>>>(lrn, 2);

    dim3 grid(NC_PAD / BN, N_TOK / BM);   // (33, 64)
    gemm_mma_kernel<<<grid, 256, SMEM_TOTAL>>>(logits);

    rescue_kernel<<<N_TOK, 256>>>(logits);
    gather_kernel<<<N_TOK, 256>>>(idxf, zq, zqst);
    loss_kernel<<<1, 256>>>(sc3);
}